// round 1
// baseline (speedup 1.0000x reference)
#include <cuda_runtime.h>
#include <math.h>

#define BB 16
#define SS 1024
#define DD 1024

// ---------------- scratch (static __device__ — allocation-free) ----------------
__device__ float g_scores[BB * SS * SS];      // 64 MB raw scores
__device__ float g_add_src[BB * SS];
__device__ float g_add_tgt[BB * SS];
__device__ float g_invT_src[BB];              // 1/sqrt(len_src)
__device__ float g_invT_tgt[BB];              // 1/sqrt(len_tgt)
__device__ float g_rowmax[BB * SS], g_rowsum1[BB * SS], g_rowsumT[BB * SS];
__device__ float g_colmax[BB * SS], g_colsum1[BB * SS], g_colsumT[BB * SS];

// ---------------- kernel 0: masks + lengths ----------------
__global__ void mask_kernel(const int* __restrict__ ids_src,
                            const int* __restrict__ ids_tgt) {
    int b = blockIdx.x;
    int z = blockIdx.y;             // 0 = src, 1 = tgt
    const int* ids = (z == 0 ? ids_src : ids_tgt) + b * SS;
    float* add = (z == 0 ? g_add_src : g_add_tgt) + b * SS;
    int i = threadIdx.x;
    int id = ids[i];
    bool sp = (id == 0) || (id == 101) || (id == 102);
    add[i] = sp ? -10000.0f : 0.0f;

    int v = sp ? 0 : 1;
    #pragma unroll
    for (int o = 16; o; o >>= 1) v += __shfl_xor_sync(0xffffffffu, v, o);
    __shared__ int cnt;
    if (threadIdx.x == 0) cnt = 0;
    __syncthreads();
    if ((threadIdx.x & 31) == 0) atomicAdd(&cnt, v);
    __syncthreads();
    if (threadIdx.x == 0) {
        float inv = rsqrtf((float)cnt);
        if (z == 0) g_invT_src[b] = inv; else g_invT_tgt[b] = inv;
    }
}

// ---------------- kernel 1: batched NT GEMM, 128x128x16 tiles, f32x2 FMA ----------------
__global__ __launch_bounds__(256, 2)
void gemm_kernel(const float* __restrict__ A, const float* __restrict__ Bm) {
    const int b = blockIdx.z;
    const float* Ab = A + (size_t)b * SS * DD;
    const float* Bb = Bm + (size_t)b * SS * DD;
    float* Cb = g_scores + (size_t)b * SS * SS;

    __shared__ float As[16][128];
    __shared__ float Bs[16][128];

    const int tid = threadIdx.x;
    const int tx = tid & 15;        // 0..15 -> col group of 8
    const int ty = tid >> 4;        // 0..15 -> row group of 8
    const int row0 = blockIdx.y * 128;
    const int col0 = blockIdx.x * 128;

    const int lr = tid >> 2;        // 0..63
    const int lc = (tid & 3) * 4;   // 0,4,8,12

    unsigned long long c2[8][4];
    #pragma unroll
    for (int i = 0; i < 8; i++)
        #pragma unroll
        for (int j = 0; j < 4; j++) c2[i][j] = 0ull;

    for (int k0 = 0; k0 < DD; k0 += 16) {
        #pragma unroll
        for (int r = 0; r < 2; r++) {
            int row = lr + r * 64;
            float4 va = *(const float4*)(Ab + (size_t)(row0 + row) * DD + k0 + lc);
            As[lc + 0][row] = va.x; As[lc + 1][row] = va.y;
            As[lc + 2][row] = va.z; As[lc + 3][row] = va.w;
            float4 vb = *(const float4*)(Bb + (size_t)(col0 + row) * DD + k0 + lc);
            Bs[lc + 0][row] = vb.x; Bs[lc + 1][row] = vb.y;
            Bs[lc + 2][row] = vb.z; Bs[lc + 3][row] = vb.w;
        }
        __syncthreads();

        #pragma unroll
        for (int k = 0; k < 16; k++) {
            const unsigned long long* bp =
                (const unsigned long long*)(&Bs[k][tx * 8]);
            unsigned long long b2[4];
            #pragma unroll
            for (int j = 0; j < 4; j++) b2[j] = bp[j];

            float4 a0 = *(const float4*)(&As[k][ty * 8]);
            float4 a1 = *(const float4*)(&As[k][ty * 8 + 4]);
            float av[8] = {a0.x, a0.y, a0.z, a0.w, a1.x, a1.y, a1.z, a1.w};

            #pragma unroll
            for (int i = 0; i < 8; i++) {
                unsigned long long ad;
                asm("mov.b64 %0, {%1, %1};" : "=l"(ad) : "f"(av[i]));
                #pragma unroll
                for (int j = 0; j < 4; j++)
                    asm("fma.rn.f32x2 %0, %1, %2, %0;"
                        : "+l"(c2[i][j]) : "l"(ad), "l"(b2[j]));
            }
        }
        __syncthreads();
    }

    #pragma unroll
    for (int i = 0; i < 8; i++) {
        size_t base = (size_t)(row0 + ty * 8 + i) * SS + col0 + tx * 8;
        #pragma unroll
        for (int j = 0; j < 4; j++)
            *(unsigned long long*)(Cb + base + 2 * j) = c2[i][j];
    }
}

// ---------------- kernel 2: per-row softmax stats (mask tgt) ----------------
__global__ void rowstats_kernel() {
    int row = blockIdx.x;           // b*1024 + s
    int b = row >> 10;
    const float* sr = g_scores + (size_t)row * SS;
    const float* at = g_add_tgt + (b << 10);
    float invT = g_invT_tgt[b];

    int t0 = threadIdx.x * 4;
    float4 v = *(const float4*)(sr + t0);
    float4 a = *(const float4*)(at + t0);
    float x0 = v.x + a.x, x1 = v.y + a.y, x2 = v.z + a.z, x3 = v.w + a.w;

    float m = fmaxf(fmaxf(x0, x1), fmaxf(x2, x3));
    #pragma unroll
    for (int o = 16; o; o >>= 1) m = fmaxf(m, __shfl_xor_sync(0xffffffffu, m, o));
    __shared__ float redm[8];
    int wid = threadIdx.x >> 5, lane = threadIdx.x & 31;
    if (lane == 0) redm[wid] = m;
    __syncthreads();
    m = redm[0];
    #pragma unroll
    for (int w = 1; w < 8; w++) m = fmaxf(m, redm[w]);

    float s1 = __expf(x0 - m) + __expf(x1 - m) + __expf(x2 - m) + __expf(x3 - m);
    float sT = __expf((x0 - m) * invT) + __expf((x1 - m) * invT)
             + __expf((x2 - m) * invT) + __expf((x3 - m) * invT);
    #pragma unroll
    for (int o = 16; o; o >>= 1) {
        s1 += __shfl_xor_sync(0xffffffffu, s1, o);
        sT += __shfl_xor_sync(0xffffffffu, sT, o);
    }
    __shared__ float r1[8], rT[8];
    if (lane == 0) { r1[wid] = s1; rT[wid] = sT; }
    __syncthreads();
    if (threadIdx.x == 0) {
        float S1 = 0.f, ST = 0.f;
        #pragma unroll
        for (int w = 0; w < 8; w++) { S1 += r1[w]; ST += rT[w]; }
        g_rowmax[row] = m; g_rowsum1[row] = S1; g_rowsumT[row] = ST;
    }
}

// ---------------- kernel 3: per-column online softmax stats (mask src) ----------------
__global__ void colstats_kernel() {
    int b = blockIdx.y;
    int t = blockIdx.x * blockDim.x + threadIdx.x;
    float invT = g_invT_src[b];
    const float* sc = g_scores + (size_t)b * SS * SS + t;
    const float* as = g_add_src + (b << 10);

    float m = -INFINITY, s1 = 0.f, sT = 0.f;
    for (int s = 0; s < SS; s++) {
        float x = sc[(size_t)s * SS] + as[s];
        if (x > m) {
            float r1 = __expf(m - x), rT = __expf((m - x) * invT);
            s1 = s1 * r1 + 1.0f;
            sT = sT * rT + 1.0f;
            m = x;
        } else {
            s1 += __expf(x - m);
            sT += __expf((x - m) * invT);
        }
    }
    g_colmax[b * SS + t] = m;
    g_colsum1[b * SS + t] = s1;
    g_colsumT[b * SS + t] = sT;
}

// ---------------- kernel 4: fused output (align_matrix | align_prob) ----------------
__global__ void out_kernel(float* __restrict__ out, size_t half) {
    int row = blockIdx.x;           // b*1024 + s
    int b = row >> 10;
    const float* sr = g_scores + (size_t)row * SS;

    float rm = g_rowmax[row];
    float inv_rs1 = 1.0f / g_rowsum1[row];
    float inv_rsT = 1.0f / g_rowsumT[row];
    float adds = g_add_src[row];
    float invTr = g_invT_tgt[b];
    float invTc = g_invT_src[b];

    int t0 = threadIdx.x * 4;
    const float* at  = g_add_tgt + (b << 10);
    const float* cmP = g_colmax  + (b << 10);
    const float* c1P = g_colsum1 + (b << 10);
    const float* cTP = g_colsumT + (b << 10);

    float4 v  = *(const float4*)(sr + t0);
    float4 a  = *(const float4*)(at + t0);
    float4 cm = *(const float4*)(cmP + t0);
    float4 c1 = *(const float4*)(c1P + t0);
    float4 cT = *(const float4*)(cTP + t0);

    float xv[4] = {v.x, v.y, v.z, v.w};
    float aa[4] = {a.x, a.y, a.z, a.w};
    float cmv[4] = {cm.x, cm.y, cm.z, cm.w};
    float c1v[4] = {c1.x, c1.y, c1.z, c1.w};
    float cTv[4] = {cT.x, cT.y, cT.z, cT.w};

    float al[4], pr[4];
    #pragma unroll
    for (int j = 0; j < 4; j++) {
        float xs = xv[j] + aa[j];
        float xt = xv[j] + adds;
        float ps1 = __expf(xs - rm) * inv_rs1;
        float pt1 = __expf(xt - cmv[j]) / c1v[j];
        float psT = __expf((xs - rm) * invTr) * inv_rsT;
        float ptT = __expf((xt - cmv[j]) * invTc) / cTv[j];
        al[j] = (ps1 > 1e-3f && pt1 > 1e-3f) ? 1.0f : 0.0f;
        pr[j] = 2.0f * psT * ptT / (psT + ptT + 1e-9f);
    }
    size_t base = (size_t)row * SS + t0;
    *(float4*)(out + base)        = make_float4(al[0], al[1], al[2], al[3]);
    *(float4*)(out + half + base) = make_float4(pr[0], pr[1], pr[2], pr[3]);
}

// ---------------- launch ----------------
extern "C" void kernel_launch(void* const* d_in, const int* in_sizes, int n_in,
                              void* d_out, int out_size) {
    const float* hs  = (const float*)d_in[0];
    const float* ht  = (const float*)d_in[1];
    const int*   isr = (const int*)d_in[2];
    const int*   itg = (const int*)d_in[3];
    float* out = (float*)d_out;

    mask_kernel<<<dim3(BB, 2), SS>>>(isr, itg);
    gemm_kernel<<<dim3(SS / 128, SS / 128, BB), 256>>>(hs, ht);
    rowstats_kernel<<<BB * SS, 256>>>();
    colstats_kernel<<<dim3(SS / 256, BB), 256>>>();
    out_kernel<<<BB * SS, 256>>>(out, (size_t)out_size / 2);
}

// round 2
// speedup vs baseline: 1.2627x; 1.2627x over previous
#include <cuda_runtime.h>
#include <math.h>

#define BB 16
#define SS 1024
#define DD 1024
#define RCHUNKS 8          // row chunks for column-stats partials

// ---------------- scratch (static __device__ — allocation-free) ----------------
__device__ float g_scores[BB * SS * SS];      // 64 MB raw scores
__device__ float g_add_src[BB * SS];
__device__ float g_add_tgt[BB * SS];
__device__ float g_invT_src[BB];              // 1/sqrt(len_src)
__device__ float g_invT_tgt[BB];              // 1/sqrt(len_tgt)
__device__ float g_rowmax[BB * SS], g_rowsum1[BB * SS], g_rowsumT[BB * SS];
__device__ float g_colmax[BB * SS], g_colsum1[BB * SS], g_colsumT[BB * SS];
__device__ float g_cm[RCHUNKS][BB * SS];      // column-stat partials
__device__ float g_c1[RCHUNKS][BB * SS];
__device__ float g_cT[RCHUNKS][BB * SS];

// ---------------- kernel 0: masks + lengths ----------------
__global__ void mask_kernel(const int* __restrict__ ids_src,
                            const int* __restrict__ ids_tgt) {
    int b = blockIdx.x;
    int z = blockIdx.y;             // 0 = src, 1 = tgt
    const int* ids = (z == 0 ? ids_src : ids_tgt) + b * SS;
    float* add = (z == 0 ? g_add_src : g_add_tgt) + b * SS;
    int i = threadIdx.x;
    int id = ids[i];
    bool sp = (id == 0) || (id == 101) || (id == 102);
    add[i] = sp ? -10000.0f : 0.0f;

    int v = sp ? 0 : 1;
    #pragma unroll
    for (int o = 16; o; o >>= 1) v += __shfl_xor_sync(0xffffffffu, v, o);
    __shared__ int cnt;
    if (threadIdx.x == 0) cnt = 0;
    __syncthreads();
    if ((threadIdx.x & 31) == 0) atomicAdd(&cnt, v);
    __syncthreads();
    if (threadIdx.x == 0) {
        float inv = rsqrtf((float)cnt);
        if (z == 0) g_invT_src[b] = inv; else g_invT_tgt[b] = inv;
    }
}

// ---------------- kernel 1: batched NT GEMM, 128x128x16 tiles, f32x2 FMA ----------------
__global__ __launch_bounds__(256, 2)
void gemm_kernel(const float* __restrict__ A, const float* __restrict__ Bm) {
    const int b = blockIdx.z;
    const float* Ab = A + (size_t)b * SS * DD;
    const float* Bb = Bm + (size_t)b * SS * DD;
    float* Cb = g_scores + (size_t)b * SS * SS;

    __shared__ float As[16][128];
    __shared__ float Bs[16][128];

    const int tid = threadIdx.x;
    const int tx = tid & 15;        // 0..15 -> col group of 8
    const int ty = tid >> 4;        // 0..15 -> row group of 8
    const int row0 = blockIdx.y * 128;
    const int col0 = blockIdx.x * 128;

    const int lr = tid >> 2;        // 0..63
    const int lc = (tid & 3) * 4;   // 0,4,8,12

    unsigned long long c2[8][4];
    #pragma unroll
    for (int i = 0; i < 8; i++)
        #pragma unroll
        for (int j = 0; j < 4; j++) c2[i][j] = 0ull;

    for (int k0 = 0; k0 < DD; k0 += 16) {
        #pragma unroll
        for (int r = 0; r < 2; r++) {
            int row = lr + r * 64;
            float4 va = *(const float4*)(Ab + (size_t)(row0 + row) * DD + k0 + lc);
            As[lc + 0][row] = va.x; As[lc + 1][row] = va.y;
            As[lc + 2][row] = va.z; As[lc + 3][row] = va.w;
            float4 vb = *(const float4*)(Bb + (size_t)(col0 + row) * DD + k0 + lc);
            Bs[lc + 0][row] = vb.x; Bs[lc + 1][row] = vb.y;
            Bs[lc + 2][row] = vb.z; Bs[lc + 3][row] = vb.w;
        }
        __syncthreads();

        #pragma unroll
        for (int k = 0; k < 16; k++) {
            const unsigned long long* bp =
                (const unsigned long long*)(&Bs[k][tx * 8]);
            unsigned long long b2[4];
            #pragma unroll
            for (int j = 0; j < 4; j++) b2[j] = bp[j];

            float4 a0 = *(const float4*)(&As[k][ty * 8]);
            float4 a1 = *(const float4*)(&As[k][ty * 8 + 4]);
            float av[8] = {a0.x, a0.y, a0.z, a0.w, a1.x, a1.y, a1.z, a1.w};

            #pragma unroll
            for (int i = 0; i < 8; i++) {
                unsigned long long ad;
                asm("mov.b64 %0, {%1, %1};" : "=l"(ad) : "f"(av[i]));
                #pragma unroll
                for (int j = 0; j < 4; j++)
                    asm("fma.rn.f32x2 %0, %1, %2, %0;"
                        : "+l"(c2[i][j]) : "l"(ad), "l"(b2[j]));
            }
        }
        __syncthreads();
    }

    #pragma unroll
    for (int i = 0; i < 8; i++) {
        size_t base = (size_t)(row0 + ty * 8 + i) * SS + col0 + tx * 8;
        #pragma unroll
        for (int j = 0; j < 4; j++)
            *(unsigned long long*)(Cb + base + 2 * j) = c2[i][j];
    }
}

// ---------------- kernel 2: per-row softmax stats (mask tgt) ----------------
__global__ void rowstats_kernel() {
    int row = blockIdx.x;           // b*1024 + s
    int b = row >> 10;
    const float* sr = g_scores + (size_t)row * SS;
    const float* at = g_add_tgt + (b << 10);
    float invT = g_invT_tgt[b];

    int t0 = threadIdx.x * 4;
    float4 v = *(const float4*)(sr + t0);
    float4 a = *(const float4*)(at + t0);
    float x0 = v.x + a.x, x1 = v.y + a.y, x2 = v.z + a.z, x3 = v.w + a.w;

    float m = fmaxf(fmaxf(x0, x1), fmaxf(x2, x3));
    #pragma unroll
    for (int o = 16; o; o >>= 1) m = fmaxf(m, __shfl_xor_sync(0xffffffffu, m, o));
    __shared__ float redm[8];
    int wid = threadIdx.x >> 5, lane = threadIdx.x & 31;
    if (lane == 0) redm[wid] = m;
    __syncthreads();
    m = redm[0];
    #pragma unroll
    for (int w = 1; w < 8; w++) m = fmaxf(m, redm[w]);

    float s1 = __expf(x0 - m) + __expf(x1 - m) + __expf(x2 - m) + __expf(x3 - m);
    float sT = __expf((x0 - m) * invT) + __expf((x1 - m) * invT)
             + __expf((x2 - m) * invT) + __expf((x3 - m) * invT);
    #pragma unroll
    for (int o = 16; o; o >>= 1) {
        s1 += __shfl_xor_sync(0xffffffffu, s1, o);
        sT += __shfl_xor_sync(0xffffffffu, sT, o);
    }
    __shared__ float r1[8], rT[8];
    if (lane == 0) { r1[wid] = s1; rT[wid] = sT; }
    __syncthreads();
    if (threadIdx.x == 0) {
        float S1 = 0.f, ST = 0.f;
        #pragma unroll
        for (int w = 0; w < 8; w++) { S1 += r1[w]; ST += rT[w]; }
        g_rowmax[row] = m; g_rowsum1[row] = S1; g_rowsumT[row] = ST;
    }
}

// ---------------- kernel 3a: column-stat partials (mask src), 128 rows/block ----------------
__global__ __launch_bounds__(128)
void colpart_kernel() {
    const int b = blockIdx.z;
    const int rc = blockIdx.y;                    // row chunk 0..7
    const int col = blockIdx.x * 128 + threadIdx.x;
    const float invT = g_invT_src[b];
    const float* sc = g_scores + (size_t)b * SS * SS + (size_t)rc * 128 * SS + col;
    const float* as = g_add_src + (b << 10) + rc * 128;

    float m = -INFINITY, s1 = 0.f, sT = 0.f;
    #pragma unroll 1
    for (int s = 0; s < 128; s += 4) {
        // batch 4 independent loads for MLP, then sequential online updates
        float x0 = sc[(size_t)(s + 0) * SS] + as[s + 0];
        float x1 = sc[(size_t)(s + 1) * SS] + as[s + 1];
        float x2 = sc[(size_t)(s + 2) * SS] + as[s + 2];
        float x3 = sc[(size_t)(s + 3) * SS] + as[s + 3];
        float xs[4] = {x0, x1, x2, x3};
        #pragma unroll
        for (int j = 0; j < 4; j++) {
            float x = xs[j];
            if (x > m) {
                float r1 = __expf(m - x), rT = __expf((m - x) * invT);
                s1 = s1 * r1 + 1.0f;
                sT = sT * rT + 1.0f;
                m = x;
            } else {
                s1 += __expf(x - m);
                sT += __expf((x - m) * invT);
            }
        }
    }
    int idx = b * SS + col;
    g_cm[rc][idx] = m;
    g_c1[rc][idx] = s1;
    g_cT[rc][idx] = sT;
}

// ---------------- kernel 3b: combine column partials ----------------
__global__ void colcombine_kernel() {
    int i = blockIdx.x * blockDim.x + threadIdx.x;   // 0..BB*SS-1
    int b = i >> 10;
    float invT = g_invT_src[b];

    float M = -INFINITY;
    #pragma unroll
    for (int rc = 0; rc < RCHUNKS; rc++) M = fmaxf(M, g_cm[rc][i]);
    float S1 = 0.f, ST = 0.f;
    #pragma unroll
    for (int rc = 0; rc < RCHUNKS; rc++) {
        float d = g_cm[rc][i] - M;
        S1 += g_c1[rc][i] * __expf(d);
        ST += g_cT[rc][i] * __expf(d * invT);
    }
    g_colmax[i] = M;
    g_colsum1[i] = S1;
    g_colsumT[i] = ST;
}

// ---------------- kernel 4: fused output (align_matrix | align_prob) ----------------
__global__ void out_kernel(float* __restrict__ out, size_t half) {
    int row = blockIdx.x;           // b*1024 + s
    int b = row >> 10;
    const float* sr = g_scores + (size_t)row * SS;

    float rm = g_rowmax[row];
    float inv_rs1 = 1.0f / g_rowsum1[row];
    float inv_rsT = 1.0f / g_rowsumT[row];
    float adds = g_add_src[row];
    float invTr = g_invT_tgt[b];
    float invTc = g_invT_src[b];

    int t0 = threadIdx.x * 4;
    const float* at  = g_add_tgt + (b << 10);
    const float* cmP = g_colmax  + (b << 10);
    const float* c1P = g_colsum1 + (b << 10);
    const float* cTP = g_colsumT + (b << 10);

    float4 v  = *(const float4*)(sr + t0);
    float4 a  = *(const float4*)(at + t0);
    float4 cm = *(const float4*)(cmP + t0);
    float4 c1 = *(const float4*)(c1P + t0);
    float4 cT = *(const float4*)(cTP + t0);

    float xv[4] = {v.x, v.y, v.z, v.w};
    float aa[4] = {a.x, a.y, a.z, a.w};
    float cmv[4] = {cm.x, cm.y, cm.z, cm.w};
    float c1v[4] = {c1.x, c1.y, c1.z, c1.w};
    float cTv[4] = {cT.x, cT.y, cT.z, cT.w};

    float al[4], pr[4];
    #pragma unroll
    for (int j = 0; j < 4; j++) {
        float xs = xv[j] + aa[j];
        float xt = xv[j] + adds;
        float ps1 = __expf(xs - rm) * inv_rs1;
        float pt1 = __expf(xt - cmv[j]) / c1v[j];
        float psT = __expf((xs - rm) * invTr) * inv_rsT;
        float ptT = __expf((xt - cmv[j]) * invTc) / cTv[j];
        al[j] = (ps1 > 1e-3f && pt1 > 1e-3f) ? 1.0f : 0.0f;
        pr[j] = 2.0f * psT * ptT / (psT + ptT + 1e-9f);
    }
    size_t base = (size_t)row * SS + t0;
    *(float4*)(out + base)        = make_float4(al[0], al[1], al[2], al[3]);
    *(float4*)(out + half + base) = make_float4(pr[0], pr[1], pr[2], pr[3]);
}

// ---------------- launch ----------------
extern "C" void kernel_launch(void* const* d_in, const int* in_sizes, int n_in,
                              void* d_out, int out_size) {
    const float* hs  = (const float*)d_in[0];
    const float* ht  = (const float*)d_in[1];
    const int*   isr = (const int*)d_in[2];
    const int*   itg = (const int*)d_in[3];
    float* out = (float*)d_out;

    mask_kernel<<<dim3(BB, 2), SS>>>(isr, itg);
    gemm_kernel<<<dim3(SS / 128, SS / 128, BB), 256>>>(hs, ht);
    rowstats_kernel<<<BB * SS, 256>>>();
    colpart_kernel<<<dim3(SS / 128, RCHUNKS, BB), 128>>>();
    colcombine_kernel<<<BB * SS / 256, 256>>>();
    out_kernel<<<BB * SS, 256>>>(out, (size_t)out_size / 2);
}

// round 4
// speedup vs baseline: 1.6760x; 1.3274x over previous
#include <cuda_runtime.h>
#include <cstdint>
#include <math.h>

#define BB 16
#define SS 1024
#define DD 1024
#define RCHUNKS 8

// GEMM tiling
#define TMB 128            // CTA tile M
#define TNB 128            // CTA tile N
#define KCH 32             // K per pipeline stage
#define KC (DD / KCH)      // 32 stages of K
#define SA 36              // padded SMEM row stride (floats): (row*4+col)%32 all distinct
#define STAGE_FLOATS (2 * 128 * SA)          // A tile + B tile
#define NSTAGE 3
#define GEMM_SMEM (NSTAGE * STAGE_FLOATS * 4)  // 110592 bytes

// ---------------- scratch (static __device__ — allocation-free) ----------------
__device__ float g_scores[BB * SS * SS];
__device__ float g_add_src[BB * SS];
__device__ float g_add_tgt[BB * SS];
__device__ float g_invT_src[BB];
__device__ float g_invT_tgt[BB];
__device__ float g_rowmax[BB * SS], g_rowsum1[BB * SS], g_rowsumT[BB * SS];
__device__ float g_colmax[BB * SS], g_colsum1[BB * SS], g_colsumT[BB * SS];
__device__ float g_cm[RCHUNKS][BB * SS];
__device__ float g_c1[RCHUNKS][BB * SS];
__device__ float g_cT[RCHUNKS][BB * SS];

// ---------------- helpers ----------------
__device__ __forceinline__ uint32_t smem_u32(const void* p) {
    uint32_t a;
    asm("{ .reg .u64 t; cvta.to.shared.u64 t, %1; cvt.u32.u64 %0, t; }"
        : "=r"(a) : "l"(p));
    return a;
}

__device__ __forceinline__ void split_tf32(float v, uint32_t& hi, uint32_t& lo) {
    asm("cvt.rna.tf32.f32 %0, %1;" : "=r"(hi) : "f"(v));
    float lf = v - __uint_as_float(hi);
    asm("cvt.rna.tf32.f32 %0, %1;" : "=r"(lo) : "f"(lf));
}

__device__ __forceinline__ void mma_tf32(float* c, const uint32_t* a, const uint32_t* b) {
    asm volatile(
        "mma.sync.aligned.m16n8k8.row.col.f32.tf32.tf32.f32 "
        "{%0,%1,%2,%3}, {%4,%5,%6,%7}, {%8,%9}, {%0,%1,%2,%3};"
        : "+f"(c[0]), "+f"(c[1]), "+f"(c[2]), "+f"(c[3])
        : "r"(a[0]), "r"(a[1]), "r"(a[2]), "r"(a[3]), "r"(b[0]), "r"(b[1]));
}

__device__ __forceinline__ void cp16(uint32_t dst, const void* src) {
    asm volatile("cp.async.cg.shared.global [%0], [%1], 16;"
                 :: "r"(dst), "l"(src) : "memory");
}

// ---------------- kernel 0: masks + lengths ----------------
__global__ void mask_kernel(const int* __restrict__ ids_src,
                            const int* __restrict__ ids_tgt) {
    int b = blockIdx.x;
    int z = blockIdx.y;
    const int* ids = (z == 0 ? ids_src : ids_tgt) + b * SS;
    float* add = (z == 0 ? g_add_src : g_add_tgt) + b * SS;
    int i = threadIdx.x;
    int id = ids[i];
    bool sp = (id == 0) || (id == 101) || (id == 102);
    add[i] = sp ? -10000.0f : 0.0f;

    int v = sp ? 0 : 1;
    #pragma unroll
    for (int o = 16; o; o >>= 1) v += __shfl_xor_sync(0xffffffffu, v, o);
    __shared__ int cnt;
    if (threadIdx.x == 0) cnt = 0;
    __syncthreads();
    if ((threadIdx.x & 31) == 0) atomicAdd(&cnt, v);
    __syncthreads();
    if (threadIdx.x == 0) {
        float inv = rsqrtf((float)cnt);
        if (z == 0) g_invT_src[b] = inv; else g_invT_tgt[b] = inv;
    }
}

// ---------------- kernel 1: 3xTF32 mma.sync GEMM, 128x128 CTA tile ----------------
__global__ __launch_bounds__(256, 1)
void gemm_mma_kernel(const float* __restrict__ A, const float* __restrict__ B) {
    extern __shared__ float sm[];

    const int tid = threadIdx.x;
    const int wid = tid >> 5, lane = tid & 31;
    const int nt = blockIdx.x, mt = blockIdx.y, b = blockIdx.z;

    const float* Ag = A + ((size_t)b * SS + mt * TMB) * DD;
    const float* Bg = B + ((size_t)b * SS + nt * TNB) * DD;

    const int mbase = (wid & 1) * 64;   // 2 m-warps of 64 rows
    const int nbase = (wid >> 1) * 32;  // 4 n-warps of 32 cols

    float acc[4][4][4];
    #pragma unroll
    for (int i = 0; i < 4; i++)
        #pragma unroll
        for (int j = 0; j < 4; j++)
            #pragma unroll
            for (int k = 0; k < 4; k++) acc[i][j][k] = 0.f;

    // prefetch lambda: stage s <- K-chunk c
    auto prefetch = [&](int c, int s) {
        float* dA = sm + s * STAGE_FLOATS;
        float* dB = dA + 128 * SA;
        #pragma unroll
        for (int i = tid; i < 1024; i += 256) {
            int row = i >> 3, seg = i & 7;
            cp16(smem_u32(dA + row * SA + seg * 4),
                 Ag + (size_t)row * DD + c * KCH + seg * 4);
            cp16(smem_u32(dB + row * SA + seg * 4),
                 Bg + (size_t)row * DD + c * KCH + seg * 4);
        }
        asm volatile("cp.async.commit_group;" ::: "memory");
    };

    prefetch(0, 0);
    prefetch(1, 1);
    prefetch(2, 2);

    for (int c = 0; c < KC; c++) {
        if (c < KC - 2)      asm volatile("cp.async.wait_group 2;" ::: "memory");
        else if (c == KC - 2) asm volatile("cp.async.wait_group 1;" ::: "memory");
        else                  asm volatile("cp.async.wait_group 0;" ::: "memory");
        __syncthreads();

        int s = c % NSTAGE;
        const float* sAp = sm + s * STAGE_FLOATS;
        const float* sBp = sAp + 128 * SA;

        #pragma unroll
        for (int kk = 0; kk < KCH; kk += 8) {
            uint32_t ah[4][4], al[4][4], bh[4][2], bl[4][2];
            #pragma unroll
            for (int ms = 0; ms < 4; ms++) {
                int r0 = mbase + ms * 16 + (lane >> 2);
                #pragma unroll
                for (int rg = 0; rg < 4; rg++) {
                    int row = r0 + (rg & 1) * 8;
                    int col = kk + (lane & 3) + (rg >> 1) * 4;
                    split_tf32(sAp[row * SA + col], ah[ms][rg], al[ms][rg]);
                }
            }
            #pragma unroll
            for (int ns = 0; ns < 4; ns++) {
                int r0 = nbase + ns * 8 + (lane >> 2);
                #pragma unroll
                for (int rg = 0; rg < 2; rg++) {
                    int col = kk + (lane & 3) + rg * 4;
                    split_tf32(sBp[r0 * SA + col], bh[ns][rg], bl[ns][rg]);
                }
            }
            #pragma unroll
            for (int ms = 0; ms < 4; ms++)
                #pragma unroll
                for (int ns = 0; ns < 4; ns++) {
                    mma_tf32(acc[ms][ns], ah[ms], bh[ns]);
                    mma_tf32(acc[ms][ns], ah[ms], bl[ns]);
                    mma_tf32(acc[ms][ns], al[ms], bh[ns]);
                }
        }
        __syncthreads();
        if (c + NSTAGE < KC) prefetch(c + NSTAGE, s);
    }

    // epilogue
    float* Cb = g_scores + (size_t)b * SS * SS;
    int row0 = mt * TMB + mbase;
    int col0 = nt * TNB + nbase;
    #pragma unroll
    for (int ms = 0; ms < 4; ms++) {
        #pragma unroll
        for (int ns = 0; ns < 4; ns++) {
            int r = row0 + ms * 16 + (lane >> 2);
            int cc = col0 + ns * 8 + 2 * (lane & 3);
            *(float2*)(Cb + (size_t)r * SS + cc) =
                make_float2(acc[ms][ns][0], acc[ms][ns][1]);
            *(float2*)(Cb + (size_t)(r + 8) * SS + cc) =
                make_float2(acc[ms][ns][2], acc[ms][ns][3]);
        }
    }
}

// ---------------- kernel 2: per-row softmax stats (mask tgt) ----------------
__global__ void rowstats_kernel() {
    int row = blockIdx.x;
    int b = row >> 10;
    const float* sr = g_scores + (size_t)row * SS;
    const float* at = g_add_tgt + (b << 10);
    float invT = g_invT_tgt[b];

    int t0 = threadIdx.x * 4;
    float4 v = *(const float4*)(sr + t0);
    float4 a = *(const float4*)(at + t0);
    float x0 = v.x + a.x, x1 = v.y + a.y, x2 = v.z + a.z, x3 = v.w + a.w;

    float m = fmaxf(fmaxf(x0, x1), fmaxf(x2, x3));
    #pragma unroll
    for (int o = 16; o; o >>= 1) m = fmaxf(m, __shfl_xor_sync(0xffffffffu, m, o));
    __shared__ float redm[8];
    int wid = threadIdx.x >> 5, lane = threadIdx.x & 31;
    if (lane == 0) redm[wid] = m;
    __syncthreads();
    m = redm[0];
    #pragma unroll
    for (int w = 1; w < 8; w++) m = fmaxf(m, redm[w]);

    float s1 = __expf(x0 - m) + __expf(x1 - m) + __expf(x2 - m) + __expf(x3 - m);
    float sT = __expf((x0 - m) * invT) + __expf((x1 - m) * invT)
             + __expf((x2 - m) * invT) + __expf((x3 - m) * invT);
    #pragma unroll
    for (int o = 16; o; o >>= 1) {
        s1 += __shfl_xor_sync(0xffffffffu, s1, o);
        sT += __shfl_xor_sync(0xffffffffu, sT, o);
    }
    __shared__ float r1[8], rT[8];
    if (lane == 0) { r1[wid] = s1; rT[wid] = sT; }
    __syncthreads();
    if (threadIdx.x == 0) {
        float S1 = 0.f, ST = 0.f;
        #pragma unroll
        for (int w = 0; w < 8; w++) { S1 += r1[w]; ST += rT[w]; }
        g_rowmax[row] = m; g_rowsum1[row] = S1; g_rowsumT[row] = ST;
    }
}

// ---------------- kernel 3a: column-stat partials ----------------
__global__ __launch_bounds__(128)
void colpart_kernel() {
    const int b = blockIdx.z;
    const int rc = blockIdx.y;
    const int col = blockIdx.x * 128 + threadIdx.x;
    const float invT = g_invT_src[b];
    const float* sc = g_scores + (size_t)b * SS * SS + (size_t)rc * 128 * SS + col;
    const float* as = g_add_src + (b << 10) + rc * 128;

    float m = -INFINITY, s1 = 0.f, sT = 0.f;
    #pragma unroll 1
    for (int s = 0; s < 128; s += 4) {
        float x0 = sc[(size_t)(s + 0) * SS] + as[s + 0];
        float x1 = sc[(size_t)(s + 1) * SS] + as[s + 1];
        float x2 = sc[(size_t)(s + 2) * SS] + as[s + 2];
        float x3 = sc[(size_t)(s + 3) * SS] + as[s + 3];
        float xs[4] = {x0, x1, x2, x3};
        #pragma unroll
        for (int j = 0; j < 4; j++) {
            float x = xs[j];
            if (x > m) {
                float r1 = __expf(m - x), rT = __expf((m - x) * invT);
                s1 = s1 * r1 + 1.0f;
                sT = sT * rT + 1.0f;
                m = x;
            } else {
                s1 += __expf(x - m);
                sT += __expf((x - m) * invT);
            }
        }
    }
    int idx = b * SS + col;
    g_cm[rc][idx] = m;
    g_c1[rc][idx] = s1;
    g_cT[rc][idx] = sT;
}

// ---------------- kernel 3b: combine column partials ----------------
__global__ void colcombine_kernel() {
    int i = blockIdx.x * blockDim.x + threadIdx.x;
    int b = i >> 10;
    float invT = g_invT_src[b];

    float M = -INFINITY;
    #pragma unroll
    for (int rc = 0; rc < RCHUNKS; rc++) M = fmaxf(M, g_cm[rc][i]);
    float S1 = 0.f, ST = 0.f;
    #pragma unroll
    for (int rc = 0; rc < RCHUNKS; rc++) {
        float d = g_cm[rc][i] - M;
        S1 += g_c1[rc][i] * __expf(d);
        ST += g_cT[rc][i] * __expf(d * invT);
    }
    g_colmax[i] = M;
    g_colsum1[i] = S1;
    g_colsumT[i] = ST;
}

// ---------------- kernel 4: fused output ----------------
__global__ void out_kernel(float* __restrict__ out, size_t half) {
    int row = blockIdx.x;
    int b = row >> 10;
    const float* sr = g_scores + (size_t)row * SS;

    float rm = g_rowmax[row];
    float inv_rs1 = 1.0f / g_rowsum1[row];
    float inv_rsT = 1.0f / g_rowsumT[row];
    float adds = g_add_src[row];
    float invTr = g_invT_tgt[b];
    float invTc = g_invT_src[b];

    int t0 = threadIdx.x * 4;
    const float* at  = g_add_tgt + (b << 10);
    const float* cmP = g_colmax  + (b << 10);
    const float* c1P = g_colsum1 + (b << 10);
    const float* cTP = g_colsumT + (b << 10);

    float4 v  = *(const float4*)(sr + t0);
    float4 a  = *(const float4*)(at + t0);
    float4 cm = *(const float4*)(cmP + t0);
    float4 c1 = *(const float4*)(c1P + t0);
    float4 cT = *(const float4*)(cTP + t0);

    float xv[4] = {v.x, v.y, v.z, v.w};
    float aa[4] = {a.x, a.y, a.z, a.w};
    float cmv[4] = {cm.x, cm.y, cm.z, cm.w};
    float c1v[4] = {c1.x, c1.y, c1.z, c1.w};
    float cTv[4] = {cT.x, cT.y, cT.z, cT.w};

    float al[4], pr[4];
    #pragma unroll
    for (int j = 0; j < 4; j++) {
        float xs = xv[j] + aa[j];
        float xt = xv[j] + adds;
        float ps1 = __expf(xs - rm) * inv_rs1;
        float pt1 = __expf(xt - cmv[j]) / c1v[j];
        float psT = __expf((xs - rm) * invTr) * inv_rsT;
        float ptT = __expf((xt - cmv[j]) * invTc) / cTv[j];
        al[j] = (ps1 > 1e-3f && pt1 > 1e-3f) ? 1.0f : 0.0f;
        pr[j] = 2.0f * psT * ptT / (psT + ptT + 1e-9f);
    }
    size_t base = (size_t)row * SS + t0;
    *(float4*)(out + base)        = make_float4(al[0], al[1], al[2], al[3]);
    *(float4*)(out + half + base) = make_float4(pr[0], pr[1], pr[2], pr[3]);
}

// ---------------- launch ----------------
extern "C" void kernel_launch(void* const* d_in, const int* in_sizes, int n_in,
                              void* d_out, int out_size) {
    const float* hs  = (const float*)d_in[0];
    const float* ht  = (const float*)d_in[1];
    const int*   isr = (const int*)d_in[2];
    const int*   itg = (const int*)d_in[3];
    float* out = (float*)d_out;

    static bool attr_set = false;
    if (!attr_set) {
        cudaFuncSetAttribute(gemm_mma_kernel,
                             cudaFuncAttributeMaxDynamicSharedMemorySize, GEMM_SMEM);
        attr_set = true;
    }

    mask_kernel<<<dim3(BB, 2), SS>>>(isr, itg);
    gemm_mma_kernel<<<dim3(SS / TNB, SS / TMB, BB), 256, GEMM_SMEM>>>(hs, ht);
    rowstats_kernel<<<BB * SS, 256>>>();
    colpart_kernel<<<dim3(SS / 128, RCHUNKS, BB), 128>>>();
    colcombine_kernel<<<BB * SS / 256, 256>>>();
    out_kernel<<<BB * SS, 256>>>(out, (size_t)out_size / 2);
}